// round 15
// baseline (speedup 1.0000x reference)
#include <cuda_runtime.h>
#include <cuda_fp16.h>
#include <math.h>
#include <stdint.h>

// Problem constants
constexpr int BB = 512;      // batch (M)
constexpr int EE = 512;      // embedding dim (K)
constexpr int CC = 100000;   // classes (N)
constexpr int NT = (CC + 127) / 128;   // 782 N-tiles

// ArcFace constants (margin = 0.5)
#define COS_M   0.8775825618903728f
#define SIN_M   0.479425538604203f
#define MM_C    0.23971276930210156f
#define THRESH  (-0.8775825618903728f)
#define S_SCALE 64.0f

// ---------------------------------------------------------------------------
// Static device scratch (allocations are forbidden)
// ---------------------------------------------------------------------------
__device__ float  g_row_loss[BB];
__device__ float  g_partial[(size_t)BB * NT];
__device__ __half g_kT_h16[(size_t)CC * EE];   // knormT [C][K] fp16
__device__ __half g_emb_h16[(size_t)BB * EE];  // emb [B][K] fp16

// ---------------------------------------------------------------------------
// PTX helpers: baseline (non-'a') instructions only
// ---------------------------------------------------------------------------
__device__ __forceinline__ uint32_t smem_u32(const void* p) {
    uint32_t a;
    asm("{ .reg .u64 t; cvta.to.shared.u64 t, %1; cvt.u32.u64 %0, t; }"
        : "=r"(a) : "l"(p));
    return a;
}

__device__ __forceinline__ void ldsm_x4(uint32_t* r, uint32_t a) {
    asm volatile("ldmatrix.sync.aligned.m8n8.x4.shared.b16 {%0,%1,%2,%3}, [%4];"
        : "=r"(r[0]), "=r"(r[1]), "=r"(r[2]), "=r"(r[3]) : "r"(a));
}
__device__ __forceinline__ void mma_f16(float* d, const uint32_t* a, const uint32_t* b) {
    asm volatile(
        "mma.sync.aligned.m16n8k16.row.col.f32.f16.f16.f32 "
        "{%0,%1,%2,%3}, {%4,%5,%6,%7}, {%8,%9}, {%0,%1,%2,%3};"
        : "+f"(d[0]), "+f"(d[1]), "+f"(d[2]), "+f"(d[3])
        : "r"(a[0]), "r"(a[1]), "r"(a[2]), "r"(a[3]), "r"(b[0]), "r"(b[1]));
}
__device__ __forceinline__ void cp16(uint32_t dst, const void* src, int sz) {
    asm volatile("cp.async.cg.shared.global [%0], [%1], 16, %2;"
        :: "r"(dst), "l"(src), "r"(sz) : "memory");
}
__device__ __forceinline__ float ex2_approx(float x) {
    float r;
    asm("ex2.approx.f32 %0, %1;" : "=f"(r) : "f"(x));
    return r;
}
#define CP_COMMIT() asm volatile("cp.async.commit_group;" ::: "memory")
#define CP_WAIT0()  asm volatile("cp.async.wait_group 0;" ::: "memory")

// log2(e) * 64 : exp(64*(o-1)) = 2^(92.332482*(o-1))
#define EXP_C 92.33248262f

// ---------------------------------------------------------------------------
// Kernel 1 (fused): single pass over ker -> norms + normalized transpose fp16
// ---------------------------------------------------------------------------
__global__ __launch_bounds__(256) void prep_ker_fused(const float* __restrict__ ker) {
    __shared__ float sm[32][513];
    __shared__ float s_inv[32];

    const int tid  = threadIdx.x;
    const int lane = tid & 31;
    const int wid  = tid >> 5;
    const int c0   = blockIdx.x * 32;

    #pragma unroll
    for (int i = 0; i < 64; i++) {
        int k = wid + i * 8;
        sm[lane][k] = ker[(size_t)k * CC + (c0 + lane)];
    }
    __syncthreads();

    #pragma unroll
    for (int i = 0; i < 4; i++) {
        int c = wid + i * 8;
        float s = 0.f;
        #pragma unroll
        for (int j = 0; j < 16; j++) {
            float v = sm[c][lane + j * 32];
            s = fmaf(v, v, s);
        }
        #pragma unroll
        for (int off = 16; off > 0; off >>= 1)
            s += __shfl_xor_sync(0xffffffff, s, off);
        if (lane == 0) s_inv[c] = 1.0f / (sqrtf(s) + 1e-6f);
    }
    __syncthreads();

    #pragma unroll
    for (int i = 0; i < 4; i++) {
        int c = wid + i * 8;
        const float inv = s_inv[c];
        size_t base = (size_t)(c0 + c) * EE;
        #pragma unroll
        for (int j = 0; j < 16; j++) {
            int k = lane + j * 32;
            g_kT_h16[base + k] = __float2half(sm[c][k] * inv);
        }
    }
}

// ---------------------------------------------------------------------------
// Kernel 2: emb -> fp16
// ---------------------------------------------------------------------------
__global__ void prep_emb_kernel(const float* __restrict__ emb) {
    int i = blockIdx.x * blockDim.x + threadIdx.x;
    if (i >= BB * EE) return;
    g_emb_h16[i] = __float2half(emb[i]);
}

// ---------------------------------------------------------------------------
// Kernel 3: mma.sync fp16 GEMM, CTA tile 128x128, 128 threads,
// warp grid 2(M)x2(N), warp tile 64x64 -> LDSM traffic -33%, 32 MMAs per
// warp per k16. 3 CTAs/SM (regs<=168, smem 73.7KB). KCH=64, double buffer.
// ---------------------------------------------------------------------------
constexpr int ROWB    = 144;                  // 128B data + 16B pad (conflict-free)
constexpr int MATB    = 128 * ROWB;           // 18432 B per matrix
constexpr int STAGEB  = 2 * MATB;             // 36864 B per stage (A, B)
constexpr int DYNB    = 2 * STAGEB;           // 73728 B dynamic smem

__global__ __launch_bounds__(128, 3) void gemm_mma_kernel(
    const int* __restrict__ label,
    float* __restrict__ out_logits, float* __restrict__ out_cos)
{
    extern __shared__ char dyn[];
    __shared__ float srows[128 * 2];

    const int tid  = threadIdx.x;
    const int lane = tid & 31;
    const int wid  = tid >> 5;     // 0..3
    const int wm   = wid >> 1;     // 0..1 (M warp)
    const int wn   = wid & 1;      // 0..1 (N warp)
    const int r0 = blockIdx.x * 128;
    const int c0 = blockIdx.y * 128;
    const uint32_t sbase = smem_u32(dyn);

    float acc[4][8][4];            // 4 m16 x 8 n8 x 4 = 64x64 warp tile
    #pragma unroll
    for (int mt = 0; mt < 4; mt++)
        #pragma unroll
        for (int nt = 0; nt < 8; nt++)
            #pragma unroll
            for (int v = 0; v < 4; v++) acc[mt][nt][v] = 0.f;

    // ---- G->S: 2048 16B-chunks per stage (2 mats x 128 rows x 8), 16/thread --
    auto load_stage = [&](int s, int kc) {
        const uint32_t stg = sbase + s * STAGEB;
        #pragma unroll
        for (int i = 0; i < 16; i++) {
            int f   = tid + i * 128;
            int m   = f >> 10;         // 0:A 1:B
            int c   = f & 1023;
            int row = c >> 3;
            int ch  = c & 7;
            uint32_t dst = stg + (uint32_t)(m * MATB + row * ROWB + ch * 16);
            const __half* src;
            int sz = 16;
            if (m == 0) {
                src = g_emb_h16 + (size_t)(r0 + row) * EE + kc * 64 + ch * 8;
            } else {
                src = g_kT_h16 + (size_t)(c0 + row) * EE + kc * 64 + ch * 8;
                if (c0 + row >= CC) sz = 0;
            }
            cp16(dst, src, sz);
        }
    };

    auto compute_stage = [&](int s) {
        const uint32_t st = sbase + s * STAGEB;
        #pragma unroll
        for (int kk = 0; kk < 4; kk++) {
            uint32_t ah[4][4];
            #pragma unroll
            for (int mt = 0; mt < 4; mt++) {
                uint32_t ad = st + (uint32_t)((wm * 64 + mt * 16 + (lane & 15)) * ROWB
                                              + (lane >> 4) * 16 + kk * 32);
                ldsm_x4(ah[mt], ad);
            }
            #pragma unroll
            for (int bp = 0; bp < 4; bp++) {   // four n16 pairs -> 8 n8 tiles
                uint32_t bh[4];
                uint32_t bd = st + MATB
                            + (uint32_t)((wn * 64 + (bp * 2 + ((lane >> 4) & 1)) * 8
                                          + (lane & 7)) * ROWB
                                         + ((lane >> 3) & 1) * 16 + kk * 32);
                ldsm_x4(bh, bd);
                const int n0 = bp * 2, n1 = bp * 2 + 1;
                #pragma unroll
                for (int mt = 0; mt < 4; mt++) mma_f16(acc[mt][n0], ah[mt], bh + 0);
                #pragma unroll
                for (int mt = 0; mt < 4; mt++) mma_f16(acc[mt][n1], ah[mt], bh + 2);
            }
        }
    };

    // ---- 2-stage pipeline over 8 K-chunks of 64 ----
    load_stage(0, 0);
    CP_COMMIT();
    CP_WAIT0();
    __syncthreads();
    for (int kc = 0; kc < 8; kc++) {
        if (kc < 7) { load_stage((kc + 1) & 1, kc + 1); CP_COMMIT(); }
        compute_stage(kc & 1);
        CP_WAIT0();
        __syncthreads();
    }

    // ---- epilogue: arcface + SCALAR stores + per-row partial sum-exp ----
    const int lq = lane >> 2;
    const int lc = 2 * (lane & 3);
    int lbs[4][2];
    #pragma unroll
    for (int mt = 0; mt < 4; mt++) {
        lbs[mt][0] = label[r0 + wm * 64 + mt * 16 + lq];
        lbs[mt][1] = label[r0 + wm * 64 + mt * 16 + lq + 8];
    }

    float rsum[4][2];
    #pragma unroll
    for (int mt = 0; mt < 4; mt++) { rsum[mt][0] = 0.f; rsum[mt][1] = 0.f; }

    const bool full_tile = (c0 + 128 <= CC);   // true for 781/782 strips

    #pragma unroll
    for (int mt = 0; mt < 4; mt++) {
        #pragma unroll
        for (int nt = 0; nt < 8; nt++) {
            #pragma unroll
            for (int v = 0; v < 4; v++) {
                const int h    = v >> 1;
                const int grow = r0 + wm * 64 + mt * 16 + lq + h * 8;
                const int col  = c0 + wn * 64 + nt * 8 + lc + (v & 1);
                if (full_tile || col < CC) {
                    float cs = acc[mt][nt][v];
                    cs = fminf(1.0f, fmaxf(-1.0f, cs));
                    float o = cs;
                    if (col == lbs[mt][h]) {
                        float sn = sqrtf(fmaxf(0.f, 1.0f - cs * cs));
                        float cm = fmaf(cs, COS_M, -sn * SIN_M);
                        o = (cs - THRESH <= 0.f) ? (cs - MM_C) : cm;
                    }
                    float lg = o * S_SCALE;
                    size_t ga = (size_t)grow * CC + col;
                    out_logits[ga] = lg;
                    out_cos[ga]    = cs;
                    rsum[mt][h] += ex2_approx(fmaf(o, EXP_C, -EXP_C));
                }
            }
        }
    }

    #pragma unroll
    for (int mt = 0; mt < 4; mt++)
        #pragma unroll
        for (int h = 0; h < 2; h++) {
            float s = rsum[mt][h];
            s += __shfl_xor_sync(0xffffffff, s, 1);
            s += __shfl_xor_sync(0xffffffff, s, 2);
            rsum[mt][h] = s;
        }

    if ((lane & 3) == 0) {
        #pragma unroll
        for (int mt = 0; mt < 4; mt++)
            #pragma unroll
            for (int h = 0; h < 2; h++)
                srows[(wm * 64 + mt * 16 + lq + h * 8) * 2 + wn] = rsum[mt][h];
    }
    __syncthreads();
    {
        float s = srows[tid * 2 + 0] + srows[tid * 2 + 1];
        g_partial[(size_t)(r0 + tid) * NT + blockIdx.y] = s;
    }
}

// ---------------------------------------------------------------------------
// Kernel 4: per-row reduce of partial sum-exps -> row loss
// ---------------------------------------------------------------------------
__global__ void row_reduce_kernel(const float* __restrict__ out_logits,
                                  const int* __restrict__ label) {
    const int row = blockIdx.x;
    float s = 0.f;
    for (int i = threadIdx.x; i < NT; i += 256)
        s += g_partial[(size_t)row * NT + i];
    __shared__ float sm[256];
    sm[threadIdx.x] = s;
    __syncthreads();
    #pragma unroll
    for (int off = 128; off > 0; off >>= 1) {
        if (threadIdx.x < off) sm[threadIdx.x] += sm[threadIdx.x + off];
        __syncthreads();
    }
    if (threadIdx.x == 0) {
        float logZ = 64.0f + logf(sm[0]);
        g_row_loss[row] = logZ - out_logits[(size_t)row * CC + label[row]];
    }
}

// ---------------------------------------------------------------------------
// Kernel 5: mean over rows -> loss scalar
// ---------------------------------------------------------------------------
__global__ void final_loss_kernel(float* __restrict__ loss_out) {
    __shared__ float sm[BB];
    const int t = threadIdx.x;
    sm[t] = g_row_loss[t];
    __syncthreads();
    #pragma unroll
    for (int off = BB / 2; off > 0; off >>= 1) {
        if (t < off) sm[t] += sm[t + off];
        __syncthreads();
    }
    if (t == 0) loss_out[0] = sm[0] / (float)BB;
}

// ---------------------------------------------------------------------------
extern "C" void kernel_launch(void* const* d_in, const int* in_sizes, int n_in,
                              void* d_out, int out_size) {
    const float* emb   = (const float*)d_in[0];
    const float* ker   = (const float*)d_in[1];
    const int*   label = (const int*)d_in[2];

    float* o          = (float*)d_out;
    float* loss_ptr   = o;
    float* out_logits = o + 1;
    float* out_cos    = o + 1 + (size_t)BB * CC;

    cudaFuncSetAttribute(gemm_mma_kernel,
                         cudaFuncAttributeMaxDynamicSharedMemorySize, DYNB);

    prep_ker_fused<<<CC / 32, 256>>>(ker);
    prep_emb_kernel<<<(BB * EE + 255) / 256, 256>>>(emb);

    dim3 grid(4, NT);   // x fastest: adjacent bids share the ker N-strip in L2
    gemm_mma_kernel<<<grid, 128, DYNB>>>(label, out_logits, out_cos);

    row_reduce_kernel<<<BB, 256>>>(out_logits, label);
    final_loss_kernel<<<1, BB>>>(loss_ptr);
}

// round 16
// speedup vs baseline: 1.2211x; 1.2211x over previous
#include <cuda_runtime.h>
#include <cuda_fp16.h>
#include <math.h>
#include <stdint.h>

// Problem constants
constexpr int BB = 512;      // batch (M)
constexpr int EE = 512;      // embedding dim (K)
constexpr int CC = 100000;   // classes (N)
constexpr int NT = (CC + 127) / 128;   // 782 N-tiles

// ArcFace constants (margin = 0.5)
#define COS_M   0.8775825618903728f
#define SIN_M   0.479425538604203f
#define MM_C    0.23971276930210156f
#define THRESH  (-0.8775825618903728f)
#define S_SCALE 64.0f

// ---------------------------------------------------------------------------
// Static device scratch (allocations are forbidden)
// ---------------------------------------------------------------------------
__device__ float  g_row_loss[BB];
__device__ float  g_partial[(size_t)BB * NT];
__device__ __half g_kT_h16[(size_t)CC * EE];   // knormT [C][K] fp16
__device__ __half g_emb_h16[(size_t)BB * EE];  // emb [B][K] fp16

// ---------------------------------------------------------------------------
// PTX helpers: baseline (non-'a') instructions only
// ---------------------------------------------------------------------------
__device__ __forceinline__ uint32_t smem_u32(const void* p) {
    uint32_t a;
    asm("{ .reg .u64 t; cvta.to.shared.u64 t, %1; cvt.u32.u64 %0, t; }"
        : "=r"(a) : "l"(p));
    return a;
}

__device__ __forceinline__ void ldsm_x4(uint32_t* r, uint32_t a) {
    asm volatile("ldmatrix.sync.aligned.m8n8.x4.shared.b16 {%0,%1,%2,%3}, [%4];"
        : "=r"(r[0]), "=r"(r[1]), "=r"(r[2]), "=r"(r[3]) : "r"(a));
}
__device__ __forceinline__ void mma_f16(float* d, const uint32_t* a, const uint32_t* b) {
    asm volatile(
        "mma.sync.aligned.m16n8k16.row.col.f32.f16.f16.f32 "
        "{%0,%1,%2,%3}, {%4,%5,%6,%7}, {%8,%9}, {%0,%1,%2,%3};"
        : "+f"(d[0]), "+f"(d[1]), "+f"(d[2]), "+f"(d[3])
        : "r"(a[0]), "r"(a[1]), "r"(a[2]), "r"(a[3]), "r"(b[0]), "r"(b[1]));
}
__device__ __forceinline__ void cp16(uint32_t dst, const void* src, int sz) {
    asm volatile("cp.async.cg.shared.global [%0], [%1], 16, %2;"
        :: "r"(dst), "l"(src), "r"(sz) : "memory");
}
__device__ __forceinline__ float ex2_approx(float x) {
    float r;
    asm("ex2.approx.f32 %0, %1;" : "=f"(r) : "f"(x));
    return r;
}
#define CP_COMMIT() asm volatile("cp.async.commit_group;" ::: "memory")
#define CP_WAIT0()  asm volatile("cp.async.wait_group 0;" ::: "memory")

// log2(e) * 64 : exp(64*(o-1)) = 2^(92.332482*(o-1))
#define EXP_C 92.33248262f

// ---------------------------------------------------------------------------
// Kernel 1 (fused): single pass over ker -> norms + normalized transpose fp16
// ---------------------------------------------------------------------------
__global__ __launch_bounds__(256) void prep_ker_fused(const float* __restrict__ ker) {
    __shared__ float sm[32][513];
    __shared__ float s_inv[32];

    const int tid  = threadIdx.x;
    const int lane = tid & 31;
    const int wid  = tid >> 5;
    const int c0   = blockIdx.x * 32;

    #pragma unroll
    for (int i = 0; i < 64; i++) {
        int k = wid + i * 8;
        sm[lane][k] = ker[(size_t)k * CC + (c0 + lane)];
    }
    __syncthreads();

    #pragma unroll
    for (int i = 0; i < 4; i++) {
        int c = wid + i * 8;
        float s = 0.f;
        #pragma unroll
        for (int j = 0; j < 16; j++) {
            float v = sm[c][lane + j * 32];
            s = fmaf(v, v, s);
        }
        #pragma unroll
        for (int off = 16; off > 0; off >>= 1)
            s += __shfl_xor_sync(0xffffffff, s, off);
        if (lane == 0) s_inv[c] = 1.0f / (sqrtf(s) + 1e-6f);
    }
    __syncthreads();

    #pragma unroll
    for (int i = 0; i < 4; i++) {
        int c = wid + i * 8;
        const float inv = s_inv[c];
        size_t base = (size_t)(c0 + c) * EE;
        #pragma unroll
        for (int j = 0; j < 16; j++) {
            int k = lane + j * 32;
            g_kT_h16[base + k] = __float2half(sm[c][k] * inv);
        }
    }
}

// ---------------------------------------------------------------------------
// Kernel 2: emb -> fp16
// ---------------------------------------------------------------------------
__global__ void prep_emb_kernel(const float* __restrict__ emb) {
    int i = blockIdx.x * blockDim.x + threadIdx.x;
    if (i >= BB * EE) return;
    g_emb_h16[i] = __float2half(emb[i]);
}

// ---------------------------------------------------------------------------
// Kernel 3: mma.sync fp16 single-term GEMM + fused arcface epilogue.
// 256 threads, 2 CTAs/SM (<=128 regs), warp grid 2x4, warp tile 64x32.
// KCH=64, double buffer. Register-pipelined fragments: LDSMs for the NEXT
// fragment group issue before the MMAs of the CURRENT group.
// ---------------------------------------------------------------------------
constexpr int ROWB    = 144;                  // 128B data + 16B pad (conflict-free)
constexpr int MATB    = 128 * ROWB;           // 18432 B per matrix
constexpr int STAGEB  = 2 * MATB;             // 36864 B per stage (A, B)
constexpr int DYNB    = 2 * STAGEB;           // 73728 B dynamic smem

__global__ __launch_bounds__(256, 2) void gemm_mma_kernel(
    const int* __restrict__ label,
    float* __restrict__ out_logits, float* __restrict__ out_cos)
{
    extern __shared__ char dyn[];
    __shared__ float srows[128 * 4];

    const int tid  = threadIdx.x;
    const int lane = tid & 31;
    const int wid  = tid >> 5;
    const int wm   = wid >> 2;     // 0..1
    const int wn   = wid & 3;      // 0..3
    const int r0 = blockIdx.x * 128;
    const int c0 = blockIdx.y * 128;
    const uint32_t sbase = smem_u32(dyn);

    float acc[4][4][4];
    #pragma unroll
    for (int mt = 0; mt < 4; mt++)
        #pragma unroll
        for (int nt = 0; nt < 4; nt++)
            #pragma unroll
            for (int v = 0; v < 4; v++) acc[mt][nt][v] = 0.f;

    // ---- G->S: 2048 16B-chunks per stage (2 mats x 128 rows x 8), 8/thread ----
    auto load_stage = [&](int s, int kc) {
        const uint32_t stg = sbase + s * STAGEB;
        #pragma unroll
        for (int i = 0; i < 8; i++) {
            int f   = tid + i * 256;
            int m   = f >> 10;         // 0:A 1:B
            int c   = f & 1023;
            int row = c >> 3;
            int ch  = c & 7;
            uint32_t dst = stg + (uint32_t)(m * MATB + row * ROWB + ch * 16);
            const __half* src;
            int sz = 16;
            if (m == 0) {
                src = g_emb_h16 + (size_t)(r0 + row) * EE + kc * 64 + ch * 8;
            } else {
                src = g_kT_h16 + (size_t)(c0 + row) * EE + kc * 64 + ch * 8;
                if (c0 + row >= CC) sz = 0;
            }
            cp16(dst, src, sz);
        }
    };

    // Register-pipelined compute: ahA/ahN and bhA/bhN double buffers.
    // Per kk (4 per stage): np0: [B-next + A-next LDSMs] then 8 MMAs;
    // np1: [B-next-kk LDSM] then 8 MMAs. Every LDSM has >=8 MMAs of slack.
    auto compute_stage = [&](int s) {
        const uint32_t st = sbase + s * STAGEB;
        const uint32_t a_base = st + (uint32_t)((wm * 64 + (lane & 15)) * ROWB
                                                + (lane >> 4) * 16);
        const uint32_t b_base = st + MATB
                              + (uint32_t)((wn * 32 + ((lane >> 4) & 1) * 8
                                            + (lane & 7)) * ROWB
                                           + ((lane >> 3) & 1) * 16);
        uint32_t ahA[4][4], ahN[4][4], bhA[4], bhN[4];

        // prologue: A(kk=0), B(np=0, kk=0)
        #pragma unroll
        for (int mt = 0; mt < 4; mt++)
            ldsm_x4(ahA[mt], a_base + mt * 16 * ROWB);
        ldsm_x4(bhA, b_base);

        #pragma unroll
        for (int kk = 0; kk < 4; kk++) {
            #pragma unroll
            for (int np = 0; np < 2; np++) {
                // prefetch next B fragment group
                if (np == 0) {
                    ldsm_x4(bhN, b_base + 16 * ROWB + kk * 32);          // B(np=1, kk)
                    if (kk < 3) {
                        #pragma unroll
                        for (int mt = 0; mt < 4; mt++)                    // A(kk+1)
                            ldsm_x4(ahN[mt], a_base + mt * 16 * ROWB + (kk + 1) * 32);
                    }
                } else if (kk < 3) {
                    ldsm_x4(bhN, b_base + (kk + 1) * 32);                 // B(np=0, kk+1)
                }

                const int n0 = np * 2, n1 = np * 2 + 1;
                #pragma unroll
                for (int mt = 0; mt < 4; mt++) mma_f16(acc[mt][n0], ahA[mt], bhA + 0);
                #pragma unroll
                for (int mt = 0; mt < 4; mt++) mma_f16(acc[mt][n1], ahA[mt], bhA + 2);

                // rotate B buffers (register renaming; free after unroll)
                #pragma unroll
                for (int i = 0; i < 4; i++) { uint32_t t = bhA[i]; bhA[i] = bhN[i]; bhN[i] = t; }
            }
            // rotate A buffers
            #pragma unroll
            for (int mt = 0; mt < 4; mt++)
                #pragma unroll
                for (int i = 0; i < 4; i++) { uint32_t t = ahA[mt][i]; ahA[mt][i] = ahN[mt][i]; ahN[mt][i] = t; }
        }
    };

    // ---- 2-stage pipeline over 8 K-chunks of 64 ----
    load_stage(0, 0);
    CP_COMMIT();
    CP_WAIT0();
    __syncthreads();
    for (int kc = 0; kc < 8; kc++) {
        if (kc < 7) { load_stage((kc + 1) & 1, kc + 1); CP_COMMIT(); }
        compute_stage(kc & 1);
        CP_WAIT0();
        __syncthreads();
    }

    // ---- epilogue: arcface + SCALAR stores + per-row partial sum-exp ----
    const int lq = lane >> 2;
    const int lc = 2 * (lane & 3);
    int lbs[4][2];
    #pragma unroll
    for (int mt = 0; mt < 4; mt++) {
        lbs[mt][0] = label[r0 + wm * 64 + mt * 16 + lq];
        lbs[mt][1] = label[r0 + wm * 64 + mt * 16 + lq + 8];
    }

    float rsum[4][2];
    #pragma unroll
    for (int mt = 0; mt < 4; mt++) { rsum[mt][0] = 0.f; rsum[mt][1] = 0.f; }

    const bool full_tile = (c0 + 128 <= CC);   // true for 781/782 strips

    #pragma unroll
    for (int mt = 0; mt < 4; mt++) {
        #pragma unroll
        for (int nt = 0; nt < 4; nt++) {
            #pragma unroll
            for (int v = 0; v < 4; v++) {
                const int h    = v >> 1;
                const int grow = r0 + wm * 64 + mt * 16 + lq + h * 8;
                const int col  = c0 + wn * 32 + nt * 8 + lc + (v & 1);
                if (full_tile || col < CC) {
                    float cs = acc[mt][nt][v];
                    cs = fminf(1.0f, fmaxf(-1.0f, cs));
                    float o = cs;
                    if (col == lbs[mt][h]) {
                        float sn = sqrtf(fmaxf(0.f, 1.0f - cs * cs));
                        float cm = fmaf(cs, COS_M, -sn * SIN_M);
                        o = (cs - THRESH <= 0.f) ? (cs - MM_C) : cm;
                    }
                    float lg = o * S_SCALE;
                    size_t ga = (size_t)grow * CC + col;
                    out_logits[ga] = lg;
                    out_cos[ga]    = cs;
                    rsum[mt][h] += ex2_approx(fmaf(o, EXP_C, -EXP_C));
                }
            }
        }
    }

    #pragma unroll
    for (int mt = 0; mt < 4; mt++)
        #pragma unroll
        for (int h = 0; h < 2; h++) {
            float s = rsum[mt][h];
            s += __shfl_xor_sync(0xffffffff, s, 1);
            s += __shfl_xor_sync(0xffffffff, s, 2);
            rsum[mt][h] = s;
        }

    if ((lane & 3) == 0) {
        #pragma unroll
        for (int mt = 0; mt < 4; mt++)
            #pragma unroll
            for (int h = 0; h < 2; h++)
                srows[(wm * 64 + mt * 16 + lq + h * 8) * 4 + wn] = rsum[mt][h];
    }
    __syncthreads();
    if (tid < 128) {
        float s = srows[tid * 4 + 0] + srows[tid * 4 + 1]
                + srows[tid * 4 + 2] + srows[tid * 4 + 3];
        g_partial[(size_t)(r0 + tid) * NT + blockIdx.y] = s;
    }
}

// ---------------------------------------------------------------------------
// Kernel 4: per-row reduce of partial sum-exps -> row loss
// ---------------------------------------------------------------------------
__global__ void row_reduce_kernel(const float* __restrict__ out_logits,
                                  const int* __restrict__ label) {
    const int row = blockIdx.x;
    float s = 0.f;
    for (int i = threadIdx.x; i < NT; i += 256)
        s += g_partial[(size_t)row * NT + i];
    __shared__ float sm[256];
    sm[threadIdx.x] = s;
    __syncthreads();
    #pragma unroll
    for (int off = 128; off > 0; off >>= 1) {
        if (threadIdx.x < off) sm[threadIdx.x] += sm[threadIdx.x + off];
        __syncthreads();
    }
    if (threadIdx.x == 0) {
        float logZ = 64.0f + logf(sm[0]);
        g_row_loss[row] = logZ - out_logits[(size_t)row * CC + label[row]];
    }
}

// ---------------------------------------------------------------------------
// Kernel 5: mean over rows -> loss scalar
// ---------------------------------------------------------------------------
__global__ void final_loss_kernel(float* __restrict__ loss_out) {
    __shared__ float sm[BB];
    const int t = threadIdx.x;
    sm[t] = g_row_loss[t];
    __syncthreads();
    #pragma unroll
    for (int off = BB / 2; off > 0; off >>= 1) {
        if (t < off) sm[t] += sm[t + off];
        __syncthreads();
    }
    if (t == 0) loss_out[0] = sm[0] / (float)BB;
}

// ---------------------------------------------------------------------------
extern "C" void kernel_launch(void* const* d_in, const int* in_sizes, int n_in,
                              void* d_out, int out_size) {
    const float* emb   = (const float*)d_in[0];
    const float* ker   = (const float*)d_in[1];
    const int*   label = (const int*)d_in[2];

    float* o          = (float*)d_out;
    float* loss_ptr   = o;
    float* out_logits = o + 1;
    float* out_cos    = o + 1 + (size_t)BB * CC;

    cudaFuncSetAttribute(gemm_mma_kernel,
                         cudaFuncAttributeMaxDynamicSharedMemorySize, DYNB);

    prep_ker_fused<<<CC / 32, 256>>>(ker);
    prep_emb_kernel<<<(BB * EE + 255) / 256, 256>>>(emb);

    dim3 grid(4, NT);   // x fastest: adjacent bids share the ker N-strip in L2
    gemm_mma_kernel<<<grid, 256, DYNB>>>(label, out_logits, out_cos);

    row_reduce_kernel<<<BB, 256>>>(out_logits, label);
    final_loss_kernel<<<1, BB>>>(loss_ptr);
}

// round 17
// speedup vs baseline: 1.2525x; 1.0257x over previous
#include <cuda_runtime.h>
#include <cuda_fp16.h>
#include <math.h>
#include <stdint.h>

// Problem constants
constexpr int BB = 512;      // batch (M)
constexpr int EE = 512;      // embedding dim (K)
constexpr int CC = 100000;   // classes (N)
constexpr int NT = (CC + 127) / 128;   // 782 N-tiles

// ArcFace constants (margin = 0.5)
#define COS_M   0.8775825618903728f
#define SIN_M   0.479425538604203f
#define MM_C    0.23971276930210156f
#define THRESH  (-0.8775825618903728f)
#define S_SCALE 64.0f

// ---------------------------------------------------------------------------
// Static device scratch (allocations are forbidden)
// ---------------------------------------------------------------------------
__device__ float  g_row_loss[BB];
__device__ float  g_partial[(size_t)BB * NT];
__device__ __half g_kT_h16[(size_t)CC * EE];   // knormT [C][K] fp16
__device__ __half g_emb_h16[(size_t)BB * EE];  // emb [B][K] fp16

// ---------------------------------------------------------------------------
// PTX helpers: baseline (non-'a') instructions only
// ---------------------------------------------------------------------------
__device__ __forceinline__ uint32_t smem_u32(const void* p) {
    uint32_t a;
    asm("{ .reg .u64 t; cvta.to.shared.u64 t, %1; cvt.u32.u64 %0, t; }"
        : "=r"(a) : "l"(p));
    return a;
}

__device__ __forceinline__ void ldsm_x4(uint32_t* r, uint32_t a) {
    asm volatile("ldmatrix.sync.aligned.m8n8.x4.shared.b16 {%0,%1,%2,%3}, [%4];"
        : "=r"(r[0]), "=r"(r[1]), "=r"(r[2]), "=r"(r[3]) : "r"(a));
}
__device__ __forceinline__ void mma_f16(float* d, const uint32_t* a, const uint32_t* b) {
    asm volatile(
        "mma.sync.aligned.m16n8k16.row.col.f32.f16.f16.f32 "
        "{%0,%1,%2,%3}, {%4,%5,%6,%7}, {%8,%9}, {%0,%1,%2,%3};"
        : "+f"(d[0]), "+f"(d[1]), "+f"(d[2]), "+f"(d[3])
        : "r"(a[0]), "r"(a[1]), "r"(a[2]), "r"(a[3]), "r"(b[0]), "r"(b[1]));
}
__device__ __forceinline__ void cp16(uint32_t dst, const void* src, int sz) {
    asm volatile("cp.async.cg.shared.global [%0], [%1], 16, %2;"
        :: "r"(dst), "l"(src), "r"(sz) : "memory");
}
__device__ __forceinline__ float ex2_approx(float x) {
    float r;
    asm("ex2.approx.f32 %0, %1;" : "=f"(r) : "f"(x));
    return r;
}
// streaming (evict-first) scalar store: keeps output traffic out of hot L2
__device__ __forceinline__ void stcs(float* p, float v) {
    asm volatile("st.global.cs.f32 [%0], %1;" :: "l"(p), "f"(v) : "memory");
}
#define CP_COMMIT() asm volatile("cp.async.commit_group;" ::: "memory")
#define CP_WAIT0()  asm volatile("cp.async.wait_group 0;" ::: "memory")

// log2(e) * 64 : exp(64*(o-1)) = 2^(92.332482*(o-1))
#define EXP_C 92.33248262f

// ---------------------------------------------------------------------------
// Kernel 1 (fused): single pass over ker -> norms + normalized transpose fp16
// ---------------------------------------------------------------------------
__global__ __launch_bounds__(256) void prep_ker_fused(const float* __restrict__ ker) {
    __shared__ float sm[32][513];
    __shared__ float s_inv[32];

    const int tid  = threadIdx.x;
    const int lane = tid & 31;
    const int wid  = tid >> 5;
    const int c0   = blockIdx.x * 32;

    #pragma unroll
    for (int i = 0; i < 64; i++) {
        int k = wid + i * 8;
        sm[lane][k] = ker[(size_t)k * CC + (c0 + lane)];
    }
    __syncthreads();

    #pragma unroll
    for (int i = 0; i < 4; i++) {
        int c = wid + i * 8;
        float s = 0.f;
        #pragma unroll
        for (int j = 0; j < 16; j++) {
            float v = sm[c][lane + j * 32];
            s = fmaf(v, v, s);
        }
        #pragma unroll
        for (int off = 16; off > 0; off >>= 1)
            s += __shfl_xor_sync(0xffffffff, s, off);
        if (lane == 0) s_inv[c] = 1.0f / (sqrtf(s) + 1e-6f);
    }
    __syncthreads();

    #pragma unroll
    for (int i = 0; i < 4; i++) {
        int c = wid + i * 8;
        const float inv = s_inv[c];
        size_t base = (size_t)(c0 + c) * EE;
        #pragma unroll
        for (int j = 0; j < 16; j++) {
            int k = lane + j * 32;
            g_kT_h16[base + k] = __float2half(sm[c][k] * inv);
        }
    }
}

// ---------------------------------------------------------------------------
// Kernel 2: emb -> fp16
// ---------------------------------------------------------------------------
__global__ void prep_emb_kernel(const float* __restrict__ emb) {
    int i = blockIdx.x * blockDim.x + threadIdx.x;
    if (i >= BB * EE) return;
    g_emb_h16[i] = __float2half(emb[i]);
}

// ---------------------------------------------------------------------------
// Kernel 3: mma.sync fp16 single-term GEMM + fused arcface epilogue.
// 256 threads, 2 CTAs/SM (<=128 regs), warp grid 2x4, warp tile 64x32.
// KCH=64, double buffer. Streaming output stores (st.global.cs).
// ---------------------------------------------------------------------------
constexpr int ROWB    = 144;                  // 128B data + 16B pad (conflict-free)
constexpr int MATB    = 128 * ROWB;           // 18432 B per matrix
constexpr int STAGEB  = 2 * MATB;             // 36864 B per stage (A, B)
constexpr int DYNB    = 2 * STAGEB;           // 73728 B dynamic smem

__global__ __launch_bounds__(256, 2) void gemm_mma_kernel(
    const int* __restrict__ label,
    float* __restrict__ out_logits, float* __restrict__ out_cos)
{
    extern __shared__ char dyn[];
    __shared__ float srows[128 * 4];

    const int tid  = threadIdx.x;
    const int lane = tid & 31;
    const int wid  = tid >> 5;
    const int wm   = wid >> 2;     // 0..1
    const int wn   = wid & 3;      // 0..3
    const int r0 = blockIdx.x * 128;
    const int c0 = blockIdx.y * 128;
    const uint32_t sbase = smem_u32(dyn);

    float acc[4][4][4];
    #pragma unroll
    for (int mt = 0; mt < 4; mt++)
        #pragma unroll
        for (int nt = 0; nt < 4; nt++)
            #pragma unroll
            for (int v = 0; v < 4; v++) acc[mt][nt][v] = 0.f;

    // ---- G->S: 2048 16B-chunks per stage (2 mats x 128 rows x 8), 8/thread ----
    auto load_stage = [&](int s, int kc) {
        const uint32_t stg = sbase + s * STAGEB;
        #pragma unroll
        for (int i = 0; i < 8; i++) {
            int f   = tid + i * 256;
            int m   = f >> 10;         // 0:A 1:B
            int c   = f & 1023;
            int row = c >> 3;
            int ch  = c & 7;
            uint32_t dst = stg + (uint32_t)(m * MATB + row * ROWB + ch * 16);
            const __half* src;
            int sz = 16;
            if (m == 0) {
                src = g_emb_h16 + (size_t)(r0 + row) * EE + kc * 64 + ch * 8;
            } else {
                src = g_kT_h16 + (size_t)(c0 + row) * EE + kc * 64 + ch * 8;
                if (c0 + row >= CC) sz = 0;
            }
            cp16(dst, src, sz);
        }
    };

    auto compute_stage = [&](int s) {
        const uint32_t st = sbase + s * STAGEB;
        #pragma unroll
        for (int kk = 0; kk < 4; kk++) {
            uint32_t ah[4][4];
            #pragma unroll
            for (int mt = 0; mt < 4; mt++) {
                uint32_t ad = st + (uint32_t)((wm * 64 + mt * 16 + (lane & 15)) * ROWB
                                              + (lane >> 4) * 16 + kk * 32);
                ldsm_x4(ah[mt], ad);
            }
            #pragma unroll
            for (int np = 0; np < 2; np++) {
                uint32_t bh[4];
                uint32_t bd = st + MATB
                            + (uint32_t)((wn * 32 + (np * 2 + ((lane >> 4) & 1)) * 8
                                          + (lane & 7)) * ROWB
                                         + ((lane >> 3) & 1) * 16 + kk * 32);
                ldsm_x4(bh, bd);
                const int n0 = np * 2, n1 = np * 2 + 1;
                #pragma unroll
                for (int mt = 0; mt < 4; mt++) mma_f16(acc[mt][n0], ah[mt], bh + 0);
                #pragma unroll
                for (int mt = 0; mt < 4; mt++) mma_f16(acc[mt][n1], ah[mt], bh + 2);
            }
        }
    };

    // ---- 2-stage pipeline over 8 K-chunks of 64 ----
    load_stage(0, 0);
    CP_COMMIT();
    CP_WAIT0();
    __syncthreads();
    for (int kc = 0; kc < 8; kc++) {
        if (kc < 7) { load_stage((kc + 1) & 1, kc + 1); CP_COMMIT(); }
        compute_stage(kc & 1);
        CP_WAIT0();
        __syncthreads();
    }

    // ---- epilogue: arcface + streaming stores + per-row partial sum-exp ----
    const int lq = lane >> 2;
    const int lc = 2 * (lane & 3);
    int lbs[4][2];
    #pragma unroll
    for (int mt = 0; mt < 4; mt++) {
        lbs[mt][0] = label[r0 + wm * 64 + mt * 16 + lq];
        lbs[mt][1] = label[r0 + wm * 64 + mt * 16 + lq + 8];
    }

    float rsum[4][2];
    #pragma unroll
    for (int mt = 0; mt < 4; mt++) { rsum[mt][0] = 0.f; rsum[mt][1] = 0.f; }

    const bool full_tile = (c0 + 128 <= CC);   // true for 781/782 strips

    #pragma unroll
    for (int mt = 0; mt < 4; mt++) {
        #pragma unroll
        for (int nt = 0; nt < 4; nt++) {
            #pragma unroll
            for (int v = 0; v < 4; v++) {
                const int h    = v >> 1;
                const int grow = r0 + wm * 64 + mt * 16 + lq + h * 8;
                const int col  = c0 + wn * 32 + nt * 8 + lc + (v & 1);
                if (full_tile || col < CC) {
                    float cs = acc[mt][nt][v];
                    cs = fminf(1.0f, fmaxf(-1.0f, cs));
                    float o = cs;
                    if (col == lbs[mt][h]) {
                        float sn = sqrtf(fmaxf(0.f, 1.0f - cs * cs));
                        float cm = fmaf(cs, COS_M, -sn * SIN_M);
                        o = (cs - THRESH <= 0.f) ? (cs - MM_C) : cm;
                    }
                    float lg = o * S_SCALE;
                    size_t ga = (size_t)grow * CC + col;
                    stcs(out_logits + ga, lg);
                    stcs(out_cos + ga, cs);
                    rsum[mt][h] += ex2_approx(fmaf(o, EXP_C, -EXP_C));
                }
            }
        }
    }

    #pragma unroll
    for (int mt = 0; mt < 4; mt++)
        #pragma unroll
        for (int h = 0; h < 2; h++) {
            float s = rsum[mt][h];
            s += __shfl_xor_sync(0xffffffff, s, 1);
            s += __shfl_xor_sync(0xffffffff, s, 2);
            rsum[mt][h] = s;
        }

    if ((lane & 3) == 0) {
        #pragma unroll
        for (int mt = 0; mt < 4; mt++)
            #pragma unroll
            for (int h = 0; h < 2; h++)
                srows[(wm * 64 + mt * 16 + lq + h * 8) * 4 + wn] = rsum[mt][h];
    }
    __syncthreads();
    if (tid < 128) {
        float s = srows[tid * 4 + 0] + srows[tid * 4 + 1]
                + srows[tid * 4 + 2] + srows[tid * 4 + 3];
        g_partial[(size_t)(r0 + tid) * NT + blockIdx.y] = s;
    }
}

// ---------------------------------------------------------------------------
// Kernel 4: per-row reduce of partial sum-exps -> row loss
// ---------------------------------------------------------------------------
__global__ void row_reduce_kernel(const float* __restrict__ out_logits,
                                  const int* __restrict__ label) {
    const int row = blockIdx.x;
    float s = 0.f;
    for (int i = threadIdx.x; i < NT; i += 256)
        s += g_partial[(size_t)row * NT + i];
    __shared__ float sm[256];
    sm[threadIdx.x] = s;
    __syncthreads();
    #pragma unroll
    for (int off = 128; off > 0; off >>= 1) {
        if (threadIdx.x < off) sm[threadIdx.x] += sm[threadIdx.x + off];
        __syncthreads();
    }
    if (threadIdx.x == 0) {
        float logZ = 64.0f + logf(sm[0]);
        g_row_loss[row] = logZ - out_logits[(size_t)row * CC + label[row]];
    }
}

// ---------------------------------------------------------------------------
// Kernel 5: mean over rows -> loss scalar
// ---------------------------------------------------------------------------
__global__ void final_loss_kernel(float* __restrict__ loss_out) {
    __shared__ float sm[BB];
    const int t = threadIdx.x;
    sm[t] = g_row_loss[t];
    __syncthreads();
    #pragma unroll
    for (int off = BB / 2; off > 0; off >>= 1) {
        if (t < off) sm[t] += sm[t + off];
        __syncthreads();
    }
    if (t == 0) loss_out[0] = sm[0] / (float)BB;
}

// ---------------------------------------------------------------------------
extern "C" void kernel_launch(void* const* d_in, const int* in_sizes, int n_in,
                              void* d_out, int out_size) {
    const float* emb   = (const float*)d_in[0];
    const float* ker   = (const float*)d_in[1];
    const int*   label = (const int*)d_in[2];

    float* o          = (float*)d_out;
    float* loss_ptr   = o;
    float* out_logits = o + 1;
    float* out_cos    = o + 1 + (size_t)BB * CC;

    cudaFuncSetAttribute(gemm_mma_kernel,
                         cudaFuncAttributeMaxDynamicSharedMemorySize, DYNB);

    prep_ker_fused<<<CC / 32, 256>>>(ker);
    prep_emb_kernel<<<(BB * EE + 255) / 256, 256>>>(emb);

    dim3 grid(4, NT);   // x fastest: adjacent bids share the ker N-strip in L2
    gemm_mma_kernel<<<grid, 256, DYNB>>>(label, out_logits, out_cos);

    row_reduce_kernel<<<BB, 256>>>(out_logits, label);
    final_loss_kernel<<<1, BB>>>(loss_ptr);
}